// round 8
// baseline (speedup 1.0000x reference)
#include <cuda_runtime.h>
#include <cuda_bf16.h>
#include <math_constants.h>

#define NPARTS 24
#define MAXB   64
#define MAXC   128
#define SLOTS  8     // xyz blocks per batch (2 warp-partials each)
#define NH     2     // n-halves per channel-pair in feat path

// __device__ scratch (allocation-free per harness rules)
__device__ float2 g_part2[MAXB * SLOTS * 2 * NPARTS * 2];      // per-warp xyz halves {x,y}/{z,cnt}
__device__ float2 g_feat[MAXB * (MAXC/2) * NH * NPARTS * 2];   // per-warp {sum,max} partials

// ---------------------------------------------------------------------------
// Fused kernel. 64-thread blocks, 12 KB smem (19 blocks = 38 warps/SM).
//   blocks [0, B*SLOTS)          : xyz partial sums + counts (pair scheme)
//   blocks [B*SLOTS, +B*C/2*NH/2): feature segmented sum+max (pair scheme,
//                                  raw int4 labels, depth-3 pipeline)
// xyz blocks first -> scheduled in wave 1, finish hidden under the feature
// stream. No inter-block dependencies inside the kernel.
// ---------------------------------------------------------------------------

#define RMW1(f, k) do {                               \
    float2 _v = ap[(k) * 32];                         \
    _v.x += (f); _v.y = fmaxf(_v.y, (f));             \
    ap[(k) * 32] = _v;                                \
} while (0)

#define RMW4(f, q) do {                               \
    RMW1((f).x, (q).x);                               \
    RMW1((f).y, (q).y);                               \
    RMW1((f).z, (q).z);                               \
    RMW1((f).w, (q).w);                               \
} while (0)

__global__ __launch_bounds__(64) void fused_kernel(
    const float* __restrict__ features, const float* __restrict__ xyz,
    const int* __restrict__ labels, int N, int C, int B)
{
    const int w    = threadIdx.x >> 5;
    const int lane = threadIdx.x & 31;
    const int pair = lane >> 1;
    const int odd  = lane & 1;

    __shared__ float4 acc[2][NPARTS][16];             // 12 KB
    const int XYZB = B * SLOTS;

    if (blockIdx.x < XYZB) {
        // ----------------- xyz path -----------------
        // pair p owns one point per iter; even lane accumulates {x,y},
        // odd lane {z,count} in the two float2 halves of the float4 cell.
        float2* ap2 = (float2*)((char*)(&acc[w][0][0]) + pair * 16 + odd * 8);
        #pragma unroll
        for (int k = 0; k < NPARTS; ++k)
            ap2[k * 32] = make_float2(0.f, 0.f);
        __syncwarp();

        const int b = blockIdx.x / SLOTS;
        const int s = blockIdx.x % SLOTS;
        const int chunk = N / SLOTS;                  // points per block
        const int p0 = b * N + s * chunk + w * (chunk >> 1);
        const int iters = chunk >> 5;                 // 16 points per warp-iter

        // depth-2 prefetch
        int   pt0  = p0 + pair;
        int   lab0 = labels[pt0];
        float u0   = xyz[3*pt0 + 2*odd];              // even: x   odd: z
        float v0   = odd ? 1.f : xyz[3*pt0 + 1];      // even: y   odd: 1

        for (int i = 0; i < iters - 1; ++i) {
            const int ptn  = p0 + (i + 1) * 16 + pair;
            const int   lab1 = labels[ptn];
            const float u1   = xyz[3*ptn + 2*odd];
            const float v1   = odd ? 1.f : xyz[3*ptn + 1];
            float2 cell = ap2[lab0 * 32];
            cell.x += u0; cell.y += v0;
            ap2[lab0 * 32] = cell;
            lab0 = lab1; u0 = u1; v0 = v1;
        }
        {
            float2 cell = ap2[lab0 * 32];
            cell.x += u0; cell.y += v0;
            ap2[lab0 * 32] = cell;
        }
        __syncwarp();

        const int slot = blockIdx.x * 2 + w;          // per-warp partial slot
        for (int k = 0; k < NPARTS; ++k) {
            float2 v = ap2[k * 32];
            #pragma unroll
            for (int off = 2; off < 32; off <<= 1) {
                v.x += __shfl_xor_sync(0xFFFFFFFFu, v.x, off);
                v.y += __shfl_xor_sync(0xFFFFFFFFu, v.y, off);
            }
            if (lane < 2)   // lane0 = {sx,sy}, lane1 = {sz,cnt}
                g_part2[((size_t)slot * NPARTS + k) * 2 + odd] = v;
        }
        return;
    }

    // ----------------- feature path -----------------
    const int gwid = (blockIdx.x - XYZB) * 2 + w;
    const int tasks_per_b = (C / 2) * NH;             // 128
    const int b  = gwid / tasks_per_b;
    const int r  = gwid % tasks_per_b;
    const int cp = r >> 1;                            // channel pair
    const int h  = r & 1;                             // n-half

    float2* ap = (float2*)((char*)(&acc[w][0][0]) + pair * 16 + odd * 8);
    #pragma unroll
    for (int k = 0; k < NPARTS; ++k)
        ap[k * 32] = make_float2(0.f, -CUDART_INF_F);
    __syncwarp();

    const int c = cp * 2 + odd;
    const float4* __restrict__ fr =
        (const float4*)features + ((size_t)(b * C + c) * (N >> 2));
    const int4* __restrict__ l4 =
        (const int4*)labels + (((size_t)b * N) >> 2);

    const int half4 = N >> 3;                         // float4 words per half
    const int base  = h * half4;
    const int iters = half4 >> 4;                     // 16 words per warp-iter

    // depth-3 pipeline
    float4 f0 = __ldcs(&fr[base + pair]);
    int4   q0 = l4[base + pair];
    float4 f1 = __ldcs(&fr[base + 16 + pair]);
    int4   q1 = l4[base + 16 + pair];
    float4 f2 = __ldcs(&fr[base + 32 + pair]);
    int4   q2 = l4[base + 32 + pair];

    for (int i = 0; i < iters - 3; ++i) {
        const int nb = base + (i + 3) * 16 + pair;
        const float4 f3 = __ldcs(&fr[nb]);
        const int4   q3 = l4[nb];
        RMW4(f0, q0);
        f0 = f1; q0 = q1; f1 = f2; q1 = q2; f2 = f3; q2 = q3;
    }
    RMW4(f0, q0);
    RMW4(f1, q1);
    RMW4(f2, q2);
    __syncwarp();

    for (int k = 0; k < NPARTS; ++k) {
        float2 v = ap[k * 32];
        #pragma unroll
        for (int off = 2; off < 32; off <<= 1) {
            v.x += __shfl_xor_sync(0xFFFFFFFFu, v.x, off);
            v.y = fmaxf(v.y, __shfl_xor_sync(0xFFFFFFFFu, v.y, off));
        }
        if (lane < 2)   // lane0 = chan A total, lane1 = chan B total
            g_feat[(size_t)gwid * (2 * NPARTS) + 2 * k + odd] = v;
    }
}

// ---------------------------------------------------------------------------
// Merge: one thread per (b, channel-pair, k).
// ---------------------------------------------------------------------------
__global__ void merge_kernel(float* __restrict__ out, int C, int B)
{
    const int total = B * (C / 2) * NPARTS;
    const int i = blockIdx.x * blockDim.x + threadIdx.x;
    if (i >= total) return;
    const int k  = i % NPARTS;
    const int t  = i / NPARTS;
    const int cp = t % (C / 2);
    const int b  = t / (C / 2);

    float sx = 0.f, sy = 0.f, sz = 0.f, cnt = 0.f;
    #pragma unroll
    for (int s = 0; s < SLOTS * 2; ++s) {
        const int slot = (b * SLOTS) * 2 + s;
        const float2 xy = g_part2[((size_t)slot * NPARTS + k) * 2 + 0];
        const float2 zc = g_part2[((size_t)slot * NPARTS + k) * 2 + 1];
        sx += xy.x; sy += xy.y; sz += zc.x; cnt += zc.y;
    }
    const float denom = fmaxf(cnt, 1.f);

    const int outd = 3 + 2 * C;
    float* o = out + ((size_t)(b * NPARTS + k)) * outd;
    if (cp == 0) {
        o[0] = sx / denom;
        o[1] = sy / denom;
        o[2] = sz / denom;
    }

    const int g0 = (b * (C / 2) + cp) * NH;
    const float2 a0 = g_feat[(size_t)(g0 + 0) * (2 * NPARTS) + 2 * k + 0];
    const float2 a1 = g_feat[(size_t)(g0 + 1) * (2 * NPARTS) + 2 * k + 0];
    const float2 b0 = g_feat[(size_t)(g0 + 0) * (2 * NPARTS) + 2 * k + 1];
    const float2 b1 = g_feat[(size_t)(g0 + 1) * (2 * NPARTS) + 2 * k + 1];

    const float meanA = (a0.x + a1.x) / denom;
    const float meanB = (b0.x + b1.x) / denom;
    const float maxA  = fmaxf(a0.y, a1.y);
    const float maxB  = fmaxf(b0.y, b1.y);

    const int c0 = cp * 2;
    o[3 + c0]         = meanA;
    o[3 + c0 + 1]     = meanB;
    o[3 + C + c0]     = fmaxf(maxA - meanA, 0.f);  // empty seg: -inf -> 0
    o[3 + C + c0 + 1] = fmaxf(maxB - meanB, 0.f);
}

extern "C" void kernel_launch(void* const* d_in, const int* in_sizes, int n_in,
                              void* d_out, int out_size)
{
    const float* xyz      = (const float*)d_in[0];
    const float* features = (const float*)d_in[1];
    const int*   labels   = (const int*)d_in[2];
    float* out = (float*)d_out;

    const long long BN = in_sizes[2];                  // B*N
    const int C = (int)((long long)in_sizes[1] / BN);  // 128
    const int outd = 3 + 2 * C;                        // 259
    const int B = out_size / (NPARTS * outd);          // 64
    const int N = (int)(BN / B);                       // 16384

    const int xyz_blocks  = B * SLOTS;                 // 512
    const int feat_blocks = B * (C / 2) * NH / 2;      // 4096
    fused_kernel<<<xyz_blocks + feat_blocks, 64>>>(features, xyz, labels, N, C, B);
    merge_kernel<<<(B * (C / 2) * NPARTS + 255) / 256, 256>>>(out, C, B);
}

// round 9
// speedup vs baseline: 1.0307x; 1.0307x over previous
#include <cuda_runtime.h>
#include <cuda_bf16.h>
#include <math_constants.h>

#define NPARTS 24
#define MAXB   64
#define MAXN   16384
#define MAXC   128
#define SLOTS  8     // xyz blocks per batch (4 warp-partials each)
#define NH     2     // n-halves per channel-pair in feat kernel

// __device__ scratch (allocation-free per harness rules)
__device__ unsigned int g_labels8[(MAXB * MAXN) / 4];            // u8-packed labels, 1 MB
__device__ float  g_partf[MAXB * SLOTS * 4 * NPARTS * 4];        // [warp-slot][k][comp] xyz partials
__device__ float  g_counts[MAXB * NPARTS];                       // denominators
__device__ float2 g_feat[MAXB * (MAXC/2) * NH * NPARTS * 2];     // per-warp {sum,max} partials

// ---------------------------------------------------------------------------
// Kernel 1: xyz partials + u8 label packing.
// 128 threads (4 warps), 12 KB smem -> 19 blocks/SM. Lane owns component
// c = lane&3 (x/y/z/count) of point-octet slot g = lane>>2: 4 B cells,
// chain length 1 per 8 points, LDS.32/STS.32 conflict-free (lane-distinct
// banks), 3-step shuffle tail. Packs labels to u8 in the same pass.
// ---------------------------------------------------------------------------
__global__ __launch_bounds__(128) void xyz_kernel(
    const float* __restrict__ xyz, const int* __restrict__ labels, int N)
{
    const int b    = blockIdx.x / SLOTS;
    const int s    = blockIdx.x % SLOTS;
    const int w    = threadIdx.x >> 5;
    const int lane = threadIdx.x & 31;
    const int g    = lane >> 2;          // point-octet slot 0..7
    const int c    = lane & 3;           // component 0..3

    __shared__ float acc[4][NPARTS][32]; // 12 KB
    #pragma unroll
    for (int k = 0; k < NPARTS; ++k)
        acc[w][k][lane] = 0.f;
    __syncwarp();

    const int chunk = N / SLOTS;         // points per block (2048)
    const int p0    = b * N + s * chunk;

    // pack this chunk's labels to u8 (block-strided, independent of accum)
    const int4* __restrict__ l4 = (const int4*)labels;
    const int wbase = p0 >> 2;
    for (int t = threadIdx.x; t < (chunk >> 2); t += 128) {
        const int4 li = l4[wbase + t];
        g_labels8[wbase + t] = (unsigned)li.x | ((unsigned)li.y << 8) |
                               ((unsigned)li.z << 16) | ((unsigned)li.w << 24);
    }

    // accumulate: each warp owns chunk/4 = 512 points, 8 per iter
    const int ppw  = chunk >> 2;
    const int base = p0 + w * ppw;
    const int iters = ppw >> 3;          // 64

    // depth-2 prefetch
    int   pt   = base + g;
    int   lab0 = labels[pt];
    float v0   = (c < 3) ? xyz[3 * pt + c] : 1.0f;

    for (int i = 0; i < iters - 1; ++i) {
        const int ptn  = base + (i + 1) * 8 + g;
        const int   lab1 = labels[ptn];
        const float v1   = (c < 3) ? xyz[3 * ptn + c] : 1.0f;
        acc[w][lab0][lane] += v0;
        lab0 = lab1; v0 = v1;
    }
    acc[w][lab0][lane] += v0;
    __syncwarp();

    const int slot = blockIdx.x * 4 + w;
    for (int k = 0; k < NPARTS; ++k) {
        float v = acc[w][k][lane];
        v += __shfl_xor_sync(0xFFFFFFFFu, v, 4);
        v += __shfl_xor_sync(0xFFFFFFFFu, v, 8);
        v += __shfl_xor_sync(0xFFFFFFFFu, v, 16);
        if (lane < 4)   // lane c holds component c total
            g_partf[((size_t)slot * NPARTS + k) * 4 + c] = v;
    }
}

// ---------------------------------------------------------------------------
// Kernel 2: feat pair-scheme (R7, proven) + depth-3 pipeline.
// 2-warp blocks, 12 KB smem. Even lanes = chan c0, odd = c0+1; 16 lane-pairs
// own point columns; float2{sum,max} RMW at parity offset (conflict-free).
// ---------------------------------------------------------------------------
#define RMW1(f, k) do {                               \
    float2 _v = ap[(k) * 32];                         \
    _v.x += (f); _v.y = fmaxf(_v.y, (f));             \
    ap[(k) * 32] = _v;                                \
} while (0)

#define RMW4(f, q) do {                               \
    RMW1((f).x, (q) & 255);                           \
    RMW1((f).y, ((q) >> 8) & 255);                    \
    RMW1((f).z, ((q) >> 16) & 255);                   \
    RMW1((f).w, (q) >> 24);                           \
} while (0)

__global__ __launch_bounds__(64) void feat_kernel(
    const float* __restrict__ features, int N, int C)
{
    const int w    = threadIdx.x >> 5;
    const int lane = threadIdx.x & 31;
    const int pair = lane >> 1;
    const int odd  = lane & 1;

    const int tasks_per_b = (C / 2) * NH;         // 128
    const int gwid = blockIdx.x * 2 + w;
    const int b  = gwid / tasks_per_b;
    const int r  = gwid % tasks_per_b;
    const int cp = r >> 1;                        // channel pair
    const int h  = r & 1;                         // n-half

    __shared__ float4 acc[2][NPARTS][16];         // 12 KB
    float2* ap = (float2*)((char*)(&acc[w][0][0]) + pair * 16 + odd * 8);

    #pragma unroll
    for (int k = 0; k < NPARTS; ++k)
        ap[k * 32] = make_float2(0.f, -CUDART_INF_F);
    __syncwarp();

    const int c = cp * 2 + odd;
    const float4* __restrict__ fr =
        (const float4*)features + ((size_t)(b * C + c) * (N >> 2));
    const unsigned* __restrict__ lr = g_labels8 + (((size_t)b * N) >> 2);

    const int half4 = N >> 3;                     // float4 words per half
    const int base  = h * half4;
    const int iters = half4 >> 4;                 // 16 words per warp-iter

    // depth-3 pipeline
    float4   f0 = __ldcs(&fr[base + pair]);
    unsigned q0 = lr[base + pair];
    float4   f1 = __ldcs(&fr[base + 16 + pair]);
    unsigned q1 = lr[base + 16 + pair];
    float4   f2 = __ldcs(&fr[base + 32 + pair]);
    unsigned q2 = lr[base + 32 + pair];

    for (int i = 0; i < iters - 3; ++i) {
        const int nb = base + (i + 3) * 16 + pair;
        const float4   f3 = __ldcs(&fr[nb]);
        const unsigned q3 = lr[nb];
        RMW4(f0, q0);
        f0 = f1; q0 = q1; f1 = f2; q1 = q2; f2 = f3; q2 = q3;
    }
    RMW4(f0, q0);
    RMW4(f1, q1);
    RMW4(f2, q2);
    __syncwarp();

    for (int k = 0; k < NPARTS; ++k) {
        float2 v = ap[k * 32];
        #pragma unroll
        for (int off = 2; off < 32; off <<= 1) {
            v.x += __shfl_xor_sync(0xFFFFFFFFu, v.x, off);
            v.y = fmaxf(v.y, __shfl_xor_sync(0xFFFFFFFFu, v.y, off));
        }
        if (lane < 2)   // lane0 = chan A total, lane1 = chan B total
            g_feat[(size_t)gwid * (2 * NPARTS) + 2 * k + odd] = v;
    }
}

// ---------------------------------------------------------------------------
// Kernel 3: counts — one thread per (b,k). Sums the 32 warp-partials once,
// writes denominator + mean_xyz.
// ---------------------------------------------------------------------------
__global__ void counts_kernel(float* __restrict__ out, int C, int B)
{
    const int i = blockIdx.x * blockDim.x + threadIdx.x;
    if (i >= B * NPARTS) return;
    const int b = i / NPARTS, k = i % NPARTS;

    float sx = 0.f, sy = 0.f, sz = 0.f, cnt = 0.f;
    #pragma unroll
    for (int s = 0; s < SLOTS * 4; ++s) {
        const float4 v = *(const float4*)
            &g_partf[((size_t)(b * SLOTS * 4 + s) * NPARTS + k) * 4];
        sx += v.x; sy += v.y; sz += v.z; cnt += v.w;
    }
    const float denom = fmaxf(cnt, 1.f);
    g_counts[i] = denom;

    float* o = out + (size_t)i * (3 + 2 * C);
    o[0] = sx / denom;
    o[1] = sy / denom;
    o[2] = sz / denom;
}

// ---------------------------------------------------------------------------
// Kernel 4: merge — one thread per (b, channel-pair, k). Denominator is a
// 4 B broadcast load; combines the NH feat partials, writes mean/surface.
// ---------------------------------------------------------------------------
__global__ void merge_kernel(float* __restrict__ out, int C, int B)
{
    const int total = B * (C / 2) * NPARTS;
    const int i = blockIdx.x * blockDim.x + threadIdx.x;
    if (i >= total) return;
    const int k  = i % NPARTS;
    const int t  = i / NPARTS;
    const int cp = t % (C / 2);
    const int b  = t / (C / 2);

    const float denom = g_counts[b * NPARTS + k];

    const int g0 = (b * (C / 2) + cp) * NH;
    const float2 a0 = g_feat[(size_t)(g0 + 0) * (2 * NPARTS) + 2 * k + 0];
    const float2 a1 = g_feat[(size_t)(g0 + 1) * (2 * NPARTS) + 2 * k + 0];
    const float2 b0 = g_feat[(size_t)(g0 + 0) * (2 * NPARTS) + 2 * k + 1];
    const float2 b1 = g_feat[(size_t)(g0 + 1) * (2 * NPARTS) + 2 * k + 1];

    const float meanA = (a0.x + a1.x) / denom;
    const float meanB = (b0.x + b1.x) / denom;
    const float maxA  = fmaxf(a0.y, a1.y);
    const float maxB  = fmaxf(b0.y, b1.y);

    const int outd = 3 + 2 * C;
    float* o = out + ((size_t)(b * NPARTS + k)) * outd;
    const int c0 = cp * 2;
    o[3 + c0]         = meanA;
    o[3 + c0 + 1]     = meanB;
    o[3 + C + c0]     = fmaxf(maxA - meanA, 0.f);  // empty seg: -inf -> 0
    o[3 + C + c0 + 1] = fmaxf(maxB - meanB, 0.f);
}

extern "C" void kernel_launch(void* const* d_in, const int* in_sizes, int n_in,
                              void* d_out, int out_size)
{
    const float* xyz      = (const float*)d_in[0];
    const float* features = (const float*)d_in[1];
    const int*   labels   = (const int*)d_in[2];
    float* out = (float*)d_out;

    const long long BN = in_sizes[2];                  // B*N
    const int C = (int)((long long)in_sizes[1] / BN);  // 128
    const int outd = 3 + 2 * C;                        // 259
    const int B = out_size / (NPARTS * outd);          // 64
    const int N = (int)(BN / B);                       // 16384

    xyz_kernel<<<B * SLOTS, 128>>>(xyz, labels, N);
    feat_kernel<<<B * (C / 2) * NH / 2, 64>>>(features, N, C);
    counts_kernel<<<(B * NPARTS + 127) / 128, 128>>>(out, C, B);
    merge_kernel<<<(B * (C / 2) * NPARTS + 255) / 256, 256>>>(out, C, B);
}

// round 10
// speedup vs baseline: 1.0980x; 1.0653x over previous
#include <cuda_runtime.h>
#include <cuda_bf16.h>
#include <math_constants.h>

#define NPARTS 24
#define MAXB   64
#define MAXN   16384
#define MAXC   128
#define XSLOTS 16    // xyz blocks per batch (2 warp-partials each -> 32 slots/batch)
#define NH     2     // n-halves per channel-pair in feat path

// __device__ scratch (allocation-free per harness rules)
__device__ unsigned int g_labels8[(MAXB * MAXN) / 4];             // u8-packed labels, 1 MB
__device__ float  g_partf[MAXB * XSLOTS * 2 * NPARTS * 4];        // [warp-slot][k][comp] xyz partials
__device__ float2 g_feat[MAXB * (MAXC/2) * NH * NPARTS * 2];      // per-warp {sum,max} partials

// ---------------------------------------------------------------------------
// Kernel 1: pack labels to u8. 5 MB traffic, ~1us. Only dependency of feat.
// ---------------------------------------------------------------------------
__global__ __launch_bounds__(256) void pack_kernel(
    const int* __restrict__ labels, int BN4)
{
    const int i = blockIdx.x * blockDim.x + threadIdx.x;
    if (i < BN4) {
        const int4 li = ((const int4*)labels)[i];
        g_labels8[i] = (unsigned)li.x | ((unsigned)li.y << 8) |
                       ((unsigned)li.z << 16) | ((unsigned)li.w << 24);
    }
}

// ---------------------------------------------------------------------------
// Kernel 2: fused. 64-thread blocks, 12 KB smem (19 blocks/SM).
//   blocks [0, B*XSLOTS)   : xyz partial sums (component scheme) — wave 1,
//                            hidden under the feature stream.
//   blocks [B*XSLOTS, ...) : EXACT R7 feat path (pair scheme, u8 labels,
//                            depth-2 pipeline) — the proven 113us core.
// ---------------------------------------------------------------------------
#define RMW1(f, k) do {                               \
    float2 _v = ap[(k) * 32];                         \
    _v.x += (f); _v.y = fmaxf(_v.y, (f));             \
    ap[(k) * 32] = _v;                                \
} while (0)

#define RMW4(f, q) do {                               \
    RMW1((f).x, (q) & 255);                           \
    RMW1((f).y, ((q) >> 8) & 255);                    \
    RMW1((f).z, ((q) >> 16) & 255);                   \
    RMW1((f).w, (q) >> 24);                           \
} while (0)

__global__ __launch_bounds__(64) void fused_kernel(
    const float* __restrict__ features, const float* __restrict__ xyz,
    const int* __restrict__ labels, int N, int C, int B)
{
    const int w    = threadIdx.x >> 5;
    const int lane = threadIdx.x & 31;

    __shared__ float4 acc4[2][NPARTS][16];            // 12 KB (both paths)
    const int XYZB = B * XSLOTS;

    if (blockIdx.x < XYZB) {
        // ---------------- xyz path (component scheme) ----------------
        // lane owns component c = lane&3 (x/y/z/count) of point-octet slot
        // g = lane>>2: 4 B cells, 1 RMW per 8 points, conflict-free.
        const int g = lane >> 2;
        const int c = lane & 3;
        float* accf = (float*)&acc4[w][0][0];         // [k*64 + lane]
        #pragma unroll
        for (int k = 0; k < NPARTS; ++k)
            accf[k * 64 + lane] = 0.f;
        __syncwarp();

        const int b     = blockIdx.x / XSLOTS;
        const int s     = blockIdx.x % XSLOTS;
        const int chunk = N / XSLOTS;                 // 1024 points per block
        const int base  = b * N + s * chunk + w * (chunk >> 1);
        const int iters = chunk >> 4;                 // 8 points per warp-iter

        // depth-2 prefetch
        int   pt   = base + g;
        int   lab0 = labels[pt];
        float v0   = (c < 3) ? xyz[3 * pt + c] : 1.0f;

        for (int i = 0; i < iters - 1; ++i) {
            const int ptn  = base + (i + 1) * 8 + g;
            const int   lab1 = labels[ptn];
            const float v1   = (c < 3) ? xyz[3 * ptn + c] : 1.0f;
            accf[lab0 * 64 + lane] += v0;
            lab0 = lab1; v0 = v1;
        }
        accf[lab0 * 64 + lane] += v0;
        __syncwarp();

        const int slot = blockIdx.x * 2 + w;          // 32 slots per batch
        for (int k = 0; k < NPARTS; ++k) {
            float v = accf[k * 64 + lane];
            v += __shfl_xor_sync(0xFFFFFFFFu, v, 4);
            v += __shfl_xor_sync(0xFFFFFFFFu, v, 8);
            v += __shfl_xor_sync(0xFFFFFFFFu, v, 16);
            if (lane < 4)
                g_partf[((size_t)slot * NPARTS + k) * 4 + c] = v;
        }
        return;
    }

    // ---------------- feat path (exact R7) ----------------
    const int pair = lane >> 1;
    const int odd  = lane & 1;
    const int tasks_per_b = (C / 2) * NH;             // 128
    const int gwid = (blockIdx.x - XYZB) * 2 + w;
    const int b  = gwid / tasks_per_b;
    const int r  = gwid % tasks_per_b;
    const int cp = r >> 1;                            // channel pair
    const int h  = r & 1;                             // n-half

    float2* ap = (float2*)((char*)(&acc4[w][0][0]) + pair * 16 + odd * 8);
    #pragma unroll
    for (int k = 0; k < NPARTS; ++k)
        ap[k * 32] = make_float2(0.f, -CUDART_INF_F);
    __syncwarp();

    const int c = cp * 2 + odd;
    const float4* __restrict__ fr =
        (const float4*)features + ((size_t)(b * C + c) * (N >> 2));
    const unsigned* __restrict__ lr = g_labels8 + (((size_t)b * N) >> 2);

    const int half4 = N >> 3;                         // float4 words per half
    const int base  = h * half4;
    const int iters = half4 >> 4;                     // 16 words per warp-iter

    // depth-2 pipeline (R7-proven)
    float4   f0 = __ldcs(&fr[base + pair]);
    unsigned q0 = lr[base + pair];
    float4   f1 = __ldcs(&fr[base + 16 + pair]);
    unsigned q1 = lr[base + 16 + pair];

    for (int i = 0; i < iters - 2; ++i) {
        const int nb = base + (i + 2) * 16 + pair;
        const float4   f2 = __ldcs(&fr[nb]);
        const unsigned q2 = lr[nb];
        RMW4(f0, q0);
        f0 = f1; q0 = q1; f1 = f2; q1 = q2;
    }
    RMW4(f0, q0);
    RMW4(f1, q1);
    __syncwarp();

    for (int k = 0; k < NPARTS; ++k) {
        float2 v = ap[k * 32];
        #pragma unroll
        for (int off = 2; off < 32; off <<= 1) {
            v.x += __shfl_xor_sync(0xFFFFFFFFu, v.x, off);
            v.y = fmaxf(v.y, __shfl_xor_sync(0xFFFFFFFFu, v.y, off));
        }
        if (lane < 2)   // lane0 = chan A total, lane1 = chan B total
            g_feat[(size_t)gwid * (2 * NPARTS) + 2 * k + odd] = v;
    }
}

// ---------------------------------------------------------------------------
// Kernel 3: merge — one WARP per (b,k). Lane s reduces xyz partial slot s
// (32 slots = 32 lanes, butterfly so all lanes hold the totals), then lanes
// sweep channel pairs with coalesced output writes.
// ---------------------------------------------------------------------------
__global__ __launch_bounds__(256) void merge_kernel(
    float* __restrict__ out, int C, int B)
{
    const int warp = (blockIdx.x * blockDim.x + threadIdx.x) >> 5;
    const int lane = threadIdx.x & 31;
    if (warp >= B * NPARTS) return;
    const int b = warp / NPARTS, k = warp % NPARTS;

    // xyz totals + count
    const int slot = b * (XSLOTS * 2) + lane;         // exactly 32 slots
    float4 v = *(const float4*)&g_partf[((size_t)slot * NPARTS + k) * 4];
    #pragma unroll
    for (int off = 16; off; off >>= 1) {
        v.x += __shfl_xor_sync(0xFFFFFFFFu, v.x, off);
        v.y += __shfl_xor_sync(0xFFFFFFFFu, v.y, off);
        v.z += __shfl_xor_sync(0xFFFFFFFFu, v.z, off);
        v.w += __shfl_xor_sync(0xFFFFFFFFu, v.w, off);
    }
    const float denom = fmaxf(v.w, 1.f);

    const int outd = 3 + 2 * C;
    float* o = out + (size_t)(b * NPARTS + k) * outd;
    if (lane == 0) {
        o[0] = v.x / denom;
        o[1] = v.y / denom;
        o[2] = v.z / denom;
    }

    for (int cp = lane; cp < C / 2; cp += 32) {
        const int g0 = (b * (C / 2) + cp) * NH;
        const float2 a0 = g_feat[(size_t)(g0 + 0) * (2 * NPARTS) + 2 * k + 0];
        const float2 a1 = g_feat[(size_t)(g0 + 1) * (2 * NPARTS) + 2 * k + 0];
        const float2 b0 = g_feat[(size_t)(g0 + 0) * (2 * NPARTS) + 2 * k + 1];
        const float2 b1 = g_feat[(size_t)(g0 + 1) * (2 * NPARTS) + 2 * k + 1];

        const float meanA = (a0.x + a1.x) / denom;
        const float meanB = (b0.x + b1.x) / denom;
        const float maxA  = fmaxf(a0.y, a1.y);
        const float maxB  = fmaxf(b0.y, b1.y);

        const int c0 = cp * 2;
        o[3 + c0]         = meanA;
        o[3 + c0 + 1]     = meanB;
        o[3 + C + c0]     = fmaxf(maxA - meanA, 0.f);  // empty seg: -inf -> 0
        o[3 + C + c0 + 1] = fmaxf(maxB - meanB, 0.f);
    }
}

extern "C" void kernel_launch(void* const* d_in, const int* in_sizes, int n_in,
                              void* d_out, int out_size)
{
    const float* xyz      = (const float*)d_in[0];
    const float* features = (const float*)d_in[1];
    const int*   labels   = (const int*)d_in[2];
    float* out = (float*)d_out;

    const long long BN = in_sizes[2];                  // B*N
    const int C = (int)((long long)in_sizes[1] / BN);  // 128
    const int outd = 3 + 2 * C;                        // 259
    const int B = out_size / (NPARTS * outd);          // 64
    const int N = (int)(BN / B);                       // 16384

    const int BN4 = (int)(BN >> 2);
    pack_kernel<<<(BN4 + 255) / 256, 256>>>(labels, BN4);

    const int xyz_blocks  = B * XSLOTS;                // 1024
    const int feat_blocks = B * (C / 2) * NH / 2;      // 4096
    fused_kernel<<<xyz_blocks + feat_blocks, 64>>>(features, xyz, labels, N, C, B);

    merge_kernel<<<(B * NPARTS * 32 + 255) / 256, 256>>>(out, C, B);
}